// round 4
// baseline (speedup 1.0000x reference)
#include <cuda_runtime.h>
#include <cuda_bf16.h>
#include <cstdint>

// SpatiallyJitterColorChannels: per-(b,c) 2D roll of x[64,3,512,512] fp32.
// out[b,c,h,w] = x[b,c,(h-sh)&511,(w-sw)&511], sh/sw = shifts[b,c,:]-2, |s|<=2.
//
// R4: R2's dual-aligned-quad scheme (duplicate B-quad loads are L1 hits ->
// free; R3 proved replacing them with shuffles is a wash) with ILP=4:
//  - 8 front-batched LDG.128 per thread (higher per-thread MLP, half the
//    blocks, amortized index math).
//  - default caching on loads (preserve the L1/L2 hit window for B quads),
//    .cs evict-first on stores only (written stream has zero reuse).
//  - select offset o in {0..3} uniform per plane; blocks never straddle
//    planes (65536 f4/plane % 1024 == 0).

#define SHIFT 2

__global__ void __launch_bounds__(256) roll2d_kernel(
    const float* __restrict__ x,
    const int*   __restrict__ shifts,   // [B, C, 2] int32 in [0, 2*SHIFT]
    float*       __restrict__ out)
{
    int base  = blockIdx.x * 1024 + threadIdx.x;  // float4 index of element 0
    int plane = base >> 16;                       // / 65536 f4 per plane

    int sh = shifts[plane * 2 + 0] - SHIFT;
    int sw = shifts[plane * 2 + 1] - SHIFT;

    int qa_off = (sw > 0) ? -4 : 0;
    int o      = (sw > 0) ? 4 - sw : -sw;         // select offset, 0..3

    const float* planep = x + ((size_t)plane << 18);   // * 262144
    float4* out4 = reinterpret_cast<float4*>(out);

    float4 A[4], B[4];
    int    oidx[4];

    #pragma unroll
    for (int e = 0; e < 4; e++) {
        int idx    = base + e * 256;
        int within = idx & 65535;
        int h      = within >> 7;            // 128 f4 per row
        int w0     = (within & 127) << 2;
        int hs     = (h - sh) & 511;
        const float* rowp = planep + (hs << 9);
        int qa = (w0 + qa_off) & 511;        // aligned quad, in-row wrap
        int qb = (qa + 4) & 511;
        A[e] = *reinterpret_cast<const float4*>(rowp + qa);
        B[e] = *reinterpret_cast<const float4*>(rowp + qb);
        oidx[e] = idx;
    }

    #pragma unroll
    for (int e = 0; e < 4; e++) {
        float4 v;
        switch (o) {   // uniform per plane -> no divergence
            case 0:  v = A[e]; break;
            case 1:  v = make_float4(A[e].y, A[e].z, A[e].w, B[e].x); break;
            case 2:  v = make_float4(A[e].z, A[e].w, B[e].x, B[e].y); break;
            default: v = make_float4(A[e].w, B[e].x, B[e].y, B[e].z); break;
        }
        __stcs(out4 + oidx[e], v);
    }
}

extern "C" void kernel_launch(void* const* d_in, const int* in_sizes, int n_in,
                              void* d_out, int out_size)
{
    const float* x      = (const float*)d_in[0];
    const int*   shifts = (const int*)d_in[1];
    float*       out    = (float*)d_out;

    int n_f4   = out_size / 4;               // 12582912
    int blocks = n_f4 / 1024;                // 12288
    roll2d_kernel<<<blocks, 256>>>(x, shifts, out);
}